// round 4
// baseline (speedup 1.0000x reference)
#include <cuda_runtime.h>
#include <cuda_bf16.h>
#include <cstdint>

// ==================== constants ====================
#define BSZ    8192
#define HDIM   1024
#define KTOT   2048           // I + H
#define BTILE  128            // batch rows per CTA
#define HT     32             // h-cols per CTA (per gate)
#define NTILE  128            // 4 gates x 32 concatenated
#define KC     32             // K per chunk
#define NCHUNK (KTOT / KC)    // 64
#define PITCH  36             // padded floats per smem row (32 + 4)
#define ASZ    (128 * PITCH)  // 4608 floats per operand tile
#define STAGE_F (2 * ASZ)     // 9216 floats per stage (A + B)
#define SMEM_BYTES (2 * STAGE_F * 4)   // 73728
#define CMOFF  ((size_t)BSZ * HDIM)    // c output offset in out[]

__device__ __forceinline__ uint32_t smem_u32(const void* p) {
    uint32_t a;
    asm("{ .reg .u64 t; cvta.to.shared.u64 t, %1; cvt.u32.u64 %0, t; }" : "=r"(a) : "l"(p));
    return a;
}

__device__ __forceinline__ void cp_async16(uint32_t dst, const void* src) {
    asm volatile("cp.async.cg.shared.global [%0], [%1], 16;" :: "r"(dst), "l"(src) : "memory");
}

__device__ __forceinline__ uint32_t cvt_tf32(float f) {
    uint32_t u;
    asm("cvt.rna.tf32.f32 %0, %1;" : "=r"(u) : "f"(f));
    return u;
}

__device__ __forceinline__ void mma_tf32(float* d, const uint32_t* a, const uint32_t* b) {
    asm volatile(
        "mma.sync.aligned.m16n8k8.row.col.f32.tf32.tf32.f32 "
        "{%0,%1,%2,%3}, {%4,%5,%6,%7}, {%8,%9}, {%0,%1,%2,%3};"
        : "+f"(d[0]), "+f"(d[1]), "+f"(d[2]), "+f"(d[3])
        : "r"(a[0]), "r"(a[1]), "r"(a[2]), "r"(a[3]), "r"(b[0]), "r"(b[1]));
}

__device__ __forceinline__ float sigm(float z) {
    return __fdividef(1.0f, 1.0f + __expf(-z));
}
__device__ __forceinline__ float tanh_(float z) {
    float e = __expf(-2.0f * z);
    return (1.0f - e) * __fdividef(1.0f, 1.0f + e);
}

// ==================== fused LSTM kernel ====================
__global__ void __launch_bounds__(256) lstm_fused(
    const float* __restrict__ x,      const float* __restrict__ h_prev,
    const float* __restrict__ c_prev,
    const float* __restrict__ Wxi, const float* __restrict__ Whi,
    const float* __restrict__ Wxf, const float* __restrict__ Whf,
    const float* __restrict__ Wxc, const float* __restrict__ Whc,
    const float* __restrict__ Wxo, const float* __restrict__ Who,
    const float* __restrict__ bxi, const float* __restrict__ bhi,
    const float* __restrict__ bxf, const float* __restrict__ bhf,
    const float* __restrict__ bxc, const float* __restrict__ bhc,
    const float* __restrict__ bxo, const float* __restrict__ bho,
    float* __restrict__ out)
{
    extern __shared__ float smf[];
    const uint32_t sb = smem_u32(smf);

    const int tid   = threadIdx.x;
    const int wid   = tid >> 5;
    const int lane  = tid & 31;
    const int gid   = lane >> 2;   // group id 0..7
    const int tg    = lane & 3;    // thread-in-group 0..3
    const int warp_m = wid >> 2;   // 0..1  (64 batch rows each)
    const int warp_n = wid & 3;    // 0..3  == gate (i,f,c,o)

    const int h0 = blockIdx.x * HT;      // 32 tiles over H
    const int b0 = blockIdx.y * BTILE;   // 64 tiles over B

    // --------- cp.async producer for one chunk ----------
    auto issue_chunk = [&](int chunk) {
        const int s = chunk & 1;
        const uint32_t stb = sb + (uint32_t)(s * STAGE_F) * 4u;
        const int kbase = chunk * KC;            // global K offset (0..2047)
        const bool first_half = (kbase < 1024);  // uniform per chunk
        #pragma unroll
        for (int t = 0; t < 8; t++) {
            const int idx  = t * 256 + tid;      // 0..2047
            const int row  = (idx & 1023) >> 3;  // 0..127
            const int seg  = idx & 7;            // 0..7 (x4 floats)
            const int kofs = (first_half ? kbase : kbase - 1024) + seg * 4;
            const float* src;
            if (idx < 1024) {
                // A tile: batch rows
                const float* base = first_half ? x : h_prev;
                src = base + (size_t)(b0 + row) * 1024 + kofs;
            } else {
                // B tile: concatenated gate rows
                const int g  = row >> 5;
                const int hr = h0 + (row & 31);
                const float* wx = (g == 0) ? Wxi : (g == 1) ? Wxf : (g == 2) ? Wxc : Wxo;
                const float* wh = (g == 0) ? Whi : (g == 1) ? Whf : (g == 2) ? Whc : Who;
                const float* base = first_half ? wx : wh;
                src = base + (size_t)hr * 1024 + kofs;
            }
            const uint32_t dst = stb + (uint32_t)((idx < 1024 ? 0 : ASZ) +
                                                  row * PITCH) * 4u + (uint32_t)seg * 16u;
            cp_async16(dst, src);
        }
        asm volatile("cp.async.commit_group;" ::: "memory");
    };

    float acc[4][4][4];
    #pragma unroll
    for (int a = 0; a < 4; a++)
        #pragma unroll
        for (int b = 0; b < 4; b++)
            #pragma unroll
            for (int c = 0; c < 4; c++) acc[a][b][c] = 0.0f;

    issue_chunk(0);
    issue_chunk(1);

    for (int i = 0; i < NCHUNK; i++) {
        if (i < NCHUNK - 1) asm volatile("cp.async.wait_group 1;" ::: "memory");
        else                asm volatile("cp.async.wait_group 0;" ::: "memory");
        __syncthreads();

        const float* As = smf + (i & 1) * STAGE_F;
        const float* Bs = As + ASZ;

        #pragma unroll
        for (int k8 = 0; k8 < 4; k8++) {
            const int k0 = k8 * 8;
            uint32_t af[4][4], bf[4][2];
            #pragma unroll
            for (int mt = 0; mt < 4; mt++) {
                const int r = warp_m * 64 + mt * 16 + gid;
                const float* ap = As + r * PITCH + k0 + tg;
                af[mt][0] = cvt_tf32(ap[0]);
                af[mt][1] = cvt_tf32(ap[8 * PITCH]);
                af[mt][2] = cvt_tf32(ap[4]);
                af[mt][3] = cvt_tf32(ap[8 * PITCH + 4]);
            }
            #pragma unroll
            for (int nt = 0; nt < 4; nt++) {
                const int n = warp_n * 32 + nt * 8 + gid;
                const float* bp = Bs + n * PITCH + k0 + tg;
                bf[nt][0] = cvt_tf32(bp[0]);
                bf[nt][1] = cvt_tf32(bp[4]);
            }
            #pragma unroll
            for (int mt = 0; mt < 4; mt++)
                #pragma unroll
                for (int nt = 0; nt < 4; nt++)
                    mma_tf32(acc[mt][nt], af[mt], bf[nt]);
        }
        __syncthreads();   // all warps done reading this stage
        if (i + 2 < NCHUNK) issue_chunk(i + 2);
    }

    // --------- epilogue: exchange gates via smem ----------
    __syncthreads();   // pipeline smem dead; reuse first 64KB as 4 gate planes
    {
        float* ep = smf + warp_n * 4096;   // plane [128][32]
        #pragma unroll
        for (int mt = 0; mt < 4; mt++) {
            #pragma unroll
            for (int nt = 0; nt < 4; nt++) {
                const int r = warp_m * 64 + mt * 16 + gid;
                const int c = nt * 8 + 2 * tg;
                float2 lo = make_float2(acc[mt][nt][0], acc[mt][nt][1]);
                float2 hi = make_float2(acc[mt][nt][2], acc[mt][nt][3]);
                *(float2*)(ep + r * 32 + c)          = lo;
                *(float2*)(ep + (r + 8) * 32 + c)    = hi;
            }
        }
    }
    __syncthreads();

    {
        const int col = tid & 31;
        const int grp = tid >> 5;          // 0..7, 16 rows each
        const int h   = h0 + col;
        const float bi = bxi[h] + bhi[h];
        const float bfv = bxf[h] + bhf[h];
        const float bc = bxc[h] + bhc[h];
        const float bo = bxo[h] + bho[h];
        const float* ep = smf;

        #pragma unroll
        for (int j = 0; j < 16; j++) {
            const int r  = grp * 16 + j;
            const int gb = b0 + r;
            const int o_ = r * 32 + col;
            const float zi = ep[o_]          + bi;
            const float zf = ep[4096 + o_]   + bfv;
            const float zc = ep[8192 + o_]   + bc;
            const float zo = ep[12288 + o_]  + bo;
            const float iv = sigm(zi), fv = sigm(zf);
            const float gv = tanh_(zc), ov = sigm(zo);
            const float cp = c_prev[(size_t)gb * 1024 + h];
            const float cn = fv * cp + iv * gv;
            out[(size_t)gb * 1024 + h]         = ov * tanh_(cn);
            out[CMOFF + (size_t)gb * 1024 + h] = cn;
        }
    }
}

// ==================== launch ====================
extern "C" void kernel_launch(void* const* d_in, const int* in_sizes, int n_in,
                              void* d_out, int out_size) {
    const float* x      = (const float*)d_in[0];
    const float* h_prev = (const float*)d_in[1];
    const float* c_prev = (const float*)d_in[2];
    const float* Wxi = (const float*)d_in[3];
    const float* Whi = (const float*)d_in[4];
    const float* Wxf = (const float*)d_in[5];
    const float* Whf = (const float*)d_in[6];
    const float* Wxc = (const float*)d_in[7];
    const float* Whc = (const float*)d_in[8];
    const float* Wxo = (const float*)d_in[9];
    const float* Who = (const float*)d_in[10];
    const float* bxi = (const float*)d_in[11];
    const float* bhi = (const float*)d_in[12];
    const float* bxf = (const float*)d_in[13];
    const float* bhf = (const float*)d_in[14];
    const float* bxc = (const float*)d_in[15];
    const float* bhc = (const float*)d_in[16];
    const float* bxo = (const float*)d_in[17];
    const float* bho = (const float*)d_in[18];
    float* out = (float*)d_out;

    cudaFuncSetAttribute(lstm_fused, cudaFuncAttributeMaxDynamicSharedMemorySize, SMEM_BYTES);

    dim3 grid(HDIM / HT, BSZ / BTILE);   // (32, 64)
    lstm_fused<<<grid, 256, SMEM_BYTES>>>(
        x, h_prev, c_prev,
        Wxi, Whi, Wxf, Whf, Wxc, Whc, Wxo, Who,
        bxi, bhi, bxf, bhf, bxc, bhc, bxo, bho,
        out);
}

// round 7
// speedup vs baseline: 1.3087x; 1.3087x over previous
#include <cuda_runtime.h>
#include <cstdint>

// ==================== constants ====================
#define BSZ    8192
#define HDIM   1024
#define KTOT   2048           // I + H
#define BTILE  128            // batch rows per CTA
#define HT     32             // h-cols per CTA (per gate)
#define KC     32             // K per chunk
#define NCHUNK (KTOT / KC)    // 64
#define A_FLOATS ((size_t)BSZ * KTOT)        // 16M
#define W_FLOATS ((size_t)4 * HDIM * KTOT)   // 8M
#define CMOFF  ((size_t)BSZ * HDIM)

// per-chunk smem: A 16KB (128x32 f32, fragment order) + W 16KB (4 gates x 32n x 32k)
#define STAGE_F   8192                        // floats per stage (32KB)
#define SMEM_BYTES (2 * STAGE_F * 4)          // 65536

__device__ float g_scr[A_FLOATS + W_FLOATS];  // tf32-rounded, fragment-permuted

// ==================== helpers ====================
__device__ __forceinline__ uint32_t smem_u32(const void* p) {
    uint32_t a;
    asm("{ .reg .u64 t; cvta.to.shared.u64 t, %1; cvt.u32.u64 %0, t; }" : "=r"(a) : "l"(p));
    return a;
}
__device__ __forceinline__ void cp_async16(uint32_t dst, const void* src) {
    asm volatile("cp.async.cg.shared.global [%0], [%1], 16;" :: "r"(dst), "l"(src) : "memory");
}
// cvt.rna.tf32.f32 requires a b32 destination register (matches R4's working form)
__device__ __forceinline__ float rnd_tf32(float f) {
    uint32_t u;
    asm("cvt.rna.tf32.f32 %0, %1;" : "=r"(u) : "f"(f));
    return __uint_as_float(u);
}
__device__ __forceinline__ void mma_tf32(float* d, const uint32_t* a, const uint32_t* b) {
    asm volatile(
        "mma.sync.aligned.m16n8k8.row.col.f32.tf32.tf32.f32 "
        "{%0,%1,%2,%3}, {%4,%5,%6,%7}, {%8,%9}, {%0,%1,%2,%3};"
        : "+f"(d[0]), "+f"(d[1]), "+f"(d[2]), "+f"(d[3])
        : "r"(a[0]), "r"(a[1]), "r"(a[2]), "r"(a[3]), "r"(b[0]), "r"(b[1]));
}
__device__ __forceinline__ float sigm(float z) {
    return __fdividef(1.0f, 1.0f + __expf(-z));
}
__device__ __forceinline__ float tanh_(float z) {
    float e = __expf(-2.0f * z);
    return (1.0f - e) * __fdividef(1.0f, 1.0f + e);
}

// ==================== prep: round to tf32 + permute to fragment order ====================
// A region (16M floats): [b_blk 64][kc 64][mt 8][k8 4][lane 32] x float4
//   float4 = (S[r0][c0], S[r0+8][c0], S[r0][c0+4], S[r0+8][c0+4])
//   r0 = b_blk*128 + mt*16 + gid, c0 = kc*32 + k8*8 + tg   (gid=lane>>2, tg=lane&3)
// W region (8M floats): [g 4][h_blk 32][kc 64][nt 4][k8 4][lane 32] x float2
//   float2 = (W_g[n][k], W_g[n][k+4]);  n = h_blk*32 + nt*8 + gid, k = kc*32 + k8*8 + tg
__global__ void __launch_bounds__(256) prep_kernel(
    const float* __restrict__ x, const float* __restrict__ h,
    const float* __restrict__ Wxi, const float* __restrict__ Whi,
    const float* __restrict__ Wxf, const float* __restrict__ Whf,
    const float* __restrict__ Wxc, const float* __restrict__ Whc,
    const float* __restrict__ Wxo, const float* __restrict__ Who)
{
    const long t = (long)blockIdx.x * blockDim.x + threadIdx.x;
    const long A_V = (long)(A_FLOATS / 4);       // 4M float4 slots
    const long W_V = (long)(W_FLOATS / 2);       // 4M float2 slots
    if (t < A_V) {
        const long o = t;
        const int lane = (int)(o & 31);
        const int k8   = (int)((o >> 5) & 3);
        const int mt   = (int)((o >> 7) & 7);
        const int kc   = (int)((o >> 10) & 63);
        const int bb   = (int)(o >> 16);
        const int gid = lane >> 2, tg = lane & 3;
        const int r0 = bb * 128 + mt * 16 + gid;
        const int c0 = kc * 32 + k8 * 8 + tg;
        const float* S = (c0 < 1024) ? x : h;
        const int cc = (c0 < 1024) ? c0 : c0 - 1024;
        float4 v;
        v.x = rnd_tf32(S[(size_t)r0 * 1024 + cc]);
        v.y = rnd_tf32(S[(size_t)(r0 + 8) * 1024 + cc]);
        v.z = rnd_tf32(S[(size_t)r0 * 1024 + cc + 4]);
        v.w = rnd_tf32(S[(size_t)(r0 + 8) * 1024 + cc + 4]);
        *(float4*)(g_scr + (size_t)o * 4) = v;
    } else if (t < A_V + W_V) {
        const long o = t - A_V;
        const int lane = (int)(o & 31);
        const int k8   = (int)((o >> 5) & 3);
        const int nt   = (int)((o >> 7) & 3);
        const int kc   = (int)((o >> 9) & 63);
        const int hb   = (int)((o >> 15) & 31);
        const int g    = (int)(o >> 20);
        const int gid = lane >> 2, tg = lane & 3;
        const int n = hb * 32 + nt * 8 + gid;
        const int k = kc * 32 + k8 * 8 + tg;
        const float* wx = (g == 0) ? Wxi : (g == 1) ? Wxf : (g == 2) ? Wxc : Wxo;
        const float* wh = (g == 0) ? Whi : (g == 1) ? Whf : (g == 2) ? Whc : Who;
        const float* S = (k < 1024) ? wx : wh;
        const int kk = (k < 1024) ? k : k - 1024;
        float2 v;
        v.x = rnd_tf32(S[(size_t)n * 1024 + kk]);
        v.y = rnd_tf32(S[(size_t)n * 1024 + kk + 4]);
        *(float2*)(g_scr + A_FLOATS + (size_t)o * 2) = v;
    }
}

// ==================== main fused LSTM ====================
__global__ void __launch_bounds__(256) lstm_fused(
    const float* __restrict__ c_prev,
    const float* __restrict__ bxi, const float* __restrict__ bhi,
    const float* __restrict__ bxf, const float* __restrict__ bhf,
    const float* __restrict__ bxc, const float* __restrict__ bhc,
    const float* __restrict__ bxo, const float* __restrict__ bho,
    float* __restrict__ out)
{
    extern __shared__ float smf[];
    const uint32_t sb = smem_u32(smf);

    const int tid   = threadIdx.x;
    const int wid   = tid >> 5;
    const int lane  = tid & 31;
    const int gid   = lane >> 2;
    const int tg    = lane & 3;
    const int warp_m = wid >> 2;   // 0..1
    const int warp_n = wid & 3;    // 0..3 == gate

    const int hb = blockIdx.x;           // 0..31
    const int bb = blockIdx.y;           // 0..63
    const int h0 = hb * HT;
    const int b0 = bb * BTILE;

    // per-chunk scratch bases (floats)
    const float* Achunk0 = g_scr + (size_t)bb * 64 * 4096;           // + kc*4096
    const float* Wchunk0 = g_scr + A_FLOATS;                          // gate/hb/kc below

    auto issue_chunk = [&](int kc) {
        const int s = kc & 1;
        const uint32_t stb = sb + (uint32_t)(s * STAGE_F) * 4u;
        const float* asrc = Achunk0 + (size_t)kc * 4096;
        #pragma unroll
        for (int t = 0; t < 4; t++) {        // A: 1024 x 16B
            const int idx = t * 256 + tid;
            cp_async16(stb + (uint32_t)idx * 16u, asrc + (size_t)idx * 4);
        }
        #pragma unroll
        for (int t = 0; t < 4; t++) {        // W: 1024 x 16B (4 gates x 4KB)
            const int idx = t * 256 + tid;
            const int g  = idx >> 8;
            const int wi = idx & 255;
            const float* wsrc = Wchunk0 + (((size_t)g * 32 + hb) * 64 + kc) * 1024
                              + (size_t)wi * 4;
            cp_async16(stb + 16384u + (uint32_t)idx * 16u, wsrc);
        }
        asm volatile("cp.async.commit_group;" ::: "memory");
    };

    float acc[4][4][4];
    #pragma unroll
    for (int a = 0; a < 4; a++)
        #pragma unroll
        for (int b = 0; b < 4; b++)
            #pragma unroll
            for (int c = 0; c < 4; c++) acc[a][b][c] = 0.0f;

    issue_chunk(0);
    issue_chunk(1);

    for (int i = 0; i < NCHUNK; i++) {
        if (i < NCHUNK - 1) asm volatile("cp.async.wait_group 1;" ::: "memory");
        else                asm volatile("cp.async.wait_group 0;" ::: "memory");
        __syncthreads();

        const float4* Af = (const float4*)(smf + (i & 1) * STAGE_F);
        const float2* Bf = (const float2*)(smf + (i & 1) * STAGE_F + 4096 + warp_n * 1024);

        #pragma unroll
        for (int k8 = 0; k8 < 4; k8++) {
            uint32_t af[4][4], bf[4][2];
            #pragma unroll
            for (int mt = 0; mt < 4; mt++) {
                float4 v = Af[((warp_m * 4 + mt) * 4 + k8) * 32 + lane];
                af[mt][0] = __float_as_uint(v.x);
                af[mt][1] = __float_as_uint(v.y);
                af[mt][2] = __float_as_uint(v.z);
                af[mt][3] = __float_as_uint(v.w);
            }
            #pragma unroll
            for (int nt = 0; nt < 4; nt++) {
                float2 w = Bf[(nt * 4 + k8) * 32 + lane];
                bf[nt][0] = __float_as_uint(w.x);
                bf[nt][1] = __float_as_uint(w.y);
            }
            #pragma unroll
            for (int mt = 0; mt < 4; mt++)
                #pragma unroll
                for (int nt = 0; nt < 4; nt++)
                    mma_tf32(acc[mt][nt], af[mt], bf[nt]);
        }
        __syncthreads();
        if (i + 2 < NCHUNK) issue_chunk(i + 2);
    }

    // ---------- epilogue: gate exchange through smem ----------
    __syncthreads();
    {
        float* ep = smf + warp_n * 4096;   // plane [128][32]
        #pragma unroll
        for (int mt = 0; mt < 4; mt++) {
            #pragma unroll
            for (int nt = 0; nt < 4; nt++) {
                const int r = warp_m * 64 + mt * 16 + gid;
                const int c = nt * 8 + 2 * tg;
                *(float2*)(ep + r * 32 + c)       = make_float2(acc[mt][nt][0], acc[mt][nt][1]);
                *(float2*)(ep + (r + 8) * 32 + c) = make_float2(acc[mt][nt][2], acc[mt][nt][3]);
            }
        }
    }
    __syncthreads();

    {
        const int col = tid & 31;
        const int grp = tid >> 5;
        const int h   = h0 + col;
        const float bi  = bxi[h] + bhi[h];
        const float bfv = bxf[h] + bhf[h];
        const float bc  = bxc[h] + bhc[h];
        const float bo  = bxo[h] + bho[h];
        const float* ep = smf;

        #pragma unroll
        for (int j = 0; j < 16; j++) {
            const int r  = grp * 16 + j;
            const int gb = b0 + r;
            const int o_ = r * 32 + col;
            const float zi = ep[o_]         + bi;
            const float zf = ep[4096 + o_]  + bfv;
            const float zc = ep[8192 + o_]  + bc;
            const float zo = ep[12288 + o_] + bo;
            const float iv = sigm(zi), fv = sigm(zf);
            const float gv = tanh_(zc), ov = sigm(zo);
            const float cp = c_prev[(size_t)gb * 1024 + h];
            const float cn = fv * cp + iv * gv;
            out[(size_t)gb * 1024 + h]         = ov * tanh_(cn);
            out[CMOFF + (size_t)gb * 1024 + h] = cn;
        }
    }
}

// ==================== launch ====================
extern "C" void kernel_launch(void* const* d_in, const int* in_sizes, int n_in,
                              void* d_out, int out_size) {
    const float* x      = (const float*)d_in[0];
    const float* h_prev = (const float*)d_in[1];
    const float* c_prev = (const float*)d_in[2];
    const float* Wxi = (const float*)d_in[3];
    const float* Whi = (const float*)d_in[4];
    const float* Wxf = (const float*)d_in[5];
    const float* Whf = (const float*)d_in[6];
    const float* Wxc = (const float*)d_in[7];
    const float* Whc = (const float*)d_in[8];
    const float* Wxo = (const float*)d_in[9];
    const float* Who = (const float*)d_in[10];
    const float* bxi = (const float*)d_in[11];
    const float* bhi = (const float*)d_in[12];
    const float* bxf = (const float*)d_in[13];
    const float* bhf = (const float*)d_in[14];
    const float* bxc = (const float*)d_in[15];
    const float* bhc = (const float*)d_in[16];
    const float* bxo = (const float*)d_in[17];
    const float* bho = (const float*)d_in[18];
    float* out = (float*)d_out;

    cudaFuncSetAttribute(lstm_fused, cudaFuncAttributeMaxDynamicSharedMemorySize, SMEM_BYTES);

    // prep: 4M float4 (A) + 4M float2 (W) = 8M threads
    const long total = (long)(A_FLOATS / 4 + W_FLOATS / 2);
    prep_kernel<<<(unsigned)((total + 255) / 256), 256>>>(x, h_prev,
        Wxi, Whi, Wxf, Whf, Wxc, Whc, Wxo, Who);

    dim3 grid(HDIM / HT, BSZ / BTILE);   // (32, 64)
    lstm_fused<<<grid, 256, SMEM_BYTES>>>(
        c_prev,
        bxi, bhi, bxf, bhf, bxc, bhc, bxo, bho,
        out);
}